// round 3
// baseline (speedup 1.0000x reference)
#include <cuda_runtime.h>

#define BZ   32
#define CAP  134
#define SEQ  144
#define INV  16
#define E_SP 1072
#define E_FT 64
#define NTHR 160
#define XSTR 160

typedef unsigned long long u64;

// ---------------- f32x2 packed math helpers (sm_103a) -----------------------
__device__ __forceinline__ u64 pack2(float x, float y) {
    u64 r; asm("mov.b64 %0, {%1, %2};" : "=l"(r) : "f"(x), "f"(y)); return r;
}
__device__ __forceinline__ u64 splat2(float x) { return pack2(x, x); }
__device__ __forceinline__ u64 ffma2(u64 a, u64 b, u64 c) {
    u64 d; asm("fma.rn.f32x2 %0, %1, %2, %3;" : "=l"(d) : "l"(a), "l"(b), "l"(c)); return d;
}
__device__ __forceinline__ u64 add2(u64 a, u64 b) {
    u64 d; asm("add.rn.f32x2 %0, %1, %2;" : "=l"(d) : "l"(a), "l"(b)); return d;
}

// ---------------- device-global precomputed state (no cudaMalloc allowed) ----
__device__ int   g_rowptr[CAP + 1];
__device__ int   g_col[E_SP];
__device__ float g_invdeg[CAP];
__device__ float g_G1[INV][INV];   // Wl @ F1
__device__ float g_G2[INV][INV];   // Wr @ F1
__device__ float g_B1[INV][INV];   // A^T @ F2
__device__ float g_F2[INV][INV];   // F2
__device__ float g_V[5][INV][INV]; // combined conv taps folded with F3
__device__ float g_csF2[INV];      // column sums of F2 (for fgcn_bl term)
__device__ float g_const[INV];     // bl@F1 + fc_b

// ---------------- prep kernel: deterministic CSR + folded matrices ----------
__global__ void prep_kernel(const int* __restrict__ gei, const int* __restrict__ fei,
                            const float* __restrict__ Wl, const float* __restrict__ bl,
                            const float* __restrict__ Wr,
                            const float* __restrict__ c1w, const float* __restrict__ c2w,
                            const float* __restrict__ fcw, const float* __restrict__ fcb) {
    int tid = threadIdx.x; // 256 threads
    __shared__ int   s_deg[CAP];
    __shared__ int   s_cnt[INV][INV];
    __shared__ float s_A[INV][INV];

    if (tid < CAP) {
        int cnt = 0;
        for (int e = 0; e < E_SP; e++) if (gei[E_SP + e] == tid) cnt++;
        s_deg[tid] = cnt;
        g_invdeg[tid] = 1.0f / fmaxf((float)cnt, 1.0f);
    }
    __syncthreads();
    if (tid == 0) {
        int acc = 0;
        for (int c = 0; c < CAP; c++) { g_rowptr[c] = acc; acc += s_deg[c]; }
        g_rowptr[CAP] = acc;
    }
    __syncthreads();
    if (tid < CAP) {
        int k = g_rowptr[tid];
        for (int e = 0; e < E_SP; e++)
            if (gei[E_SP + e] == tid) g_col[k++] = gei[e];
    }
    {
        int i = tid >> 4, j = tid & 15;
        int cnt = 0;
        for (int e = 0; e < E_FT; e++)
            if (fei[E_FT + e] == i && fei[e] == j) cnt++;
        s_cnt[i][j] = cnt;
    }
    __syncthreads();
    {
        int i = tid >> 4, j = tid & 15;
        int dsum = 0;
        for (int jj = 0; jj < INV; jj++) dsum += s_cnt[i][jj];
        s_A[i][j] = (float)s_cnt[i][j] / fmaxf((float)dsum, 1.0f);
    }
    __syncthreads();
    {
        int r = tid >> 4, o = tid & 15;
        float g1 = 0.f, g2 = 0.f, b1 = 0.f;
        for (int i = 0; i < INV; i++) {
            float f1 = fcw[i * INV + o];
            float f2 = fcw[(INV + i) * INV + o];
            g1 += Wl[r * INV + i] * f1;
            g2 += Wr[r * INV + i] * f1;
            b1 += s_A[i][r] * f2;
        }
        g_G1[r][o] = g1; g_G2[r][o] = g2; g_B1[r][o] = b1;
        g_F2[r][o] = fcw[(INV + r) * INV + o];
        for (int k = 0; k < 5; k++) {
            float v = 0.f;
            for (int o2 = 0; o2 < INV; o2++) {
                float w5 = c2w[(o2 * INV + r) * 5 + k];
                if (k >= 1 && k <= 3) w5 += c1w[(o2 * INV + r) * 3 + (k - 1)];
                v += w5 * fcw[(32 + o2) * INV + o];
            }
            g_V[k][r][o] = v;
        }
        if (r == 0) {
            float cs = 0.f, cv = 0.f;
            for (int i = 0; i < INV; i++) {
                cs += fcw[(INV + i) * INV + o];
                cv += bl[i] * fcw[i * INV + o];
            }
            g_csF2[o] = cs;
            g_const[o] = cv + fcb[o];
        }
    }
}

// ---------------- main fused kernel: one (b,c) slice per block --------------
__global__ __launch_bounds__(NTHR, 3)
void stconv_kernel(const float* __restrict__ src,
                   const float* __restrict__ fWl, const float* __restrict__ fWr,
                   const float* __restrict__ fbl,
                   float* __restrict__ out) {
    __shared__ __align__(16) float sX[INV][XSTR];
    __shared__ __align__(16) float sYA[SEQ][INV];
    __shared__ __align__(16) float sYF[SEQ][INV];
    __shared__ __align__(16) float sG1[INV][INV], sG2[INV][INV], sB1[INV][INV], sF2[INV][INV];
    __shared__ __align__(16) float sV[5][INV][INV];
    __shared__ float sCs[INV], sC0[INV];

    const int c = blockIdx.x, b = blockIdx.y;
    const int tid = threadIdx.x;
    const int s = tid;
    const int base = ((b * CAP + c) * SEQ) * INV;

    for (int idx = tid; idx < INV * INV; idx += NTHR) {
        int r = idx >> 4, o = idx & 15;
        sG1[r][o] = g_G1[r][o]; sG2[r][o] = g_G2[r][o];
        sB1[r][o] = g_B1[r][o]; sF2[r][o] = g_F2[r][o];
        #pragma unroll
        for (int k = 0; k < 5; k++) sV[k][r][o] = g_V[k][r][o];
        if (r == 0) { sCs[o] = g_csF2[o]; sC0[o] = g_const[o]; }
    }

    float xrow[16];
    if (s < SEQ) {
        const float4* p = (const float4*)(src + base + s * INV);
        float4 a0 = p[0], a1 = p[1], a2 = p[2], a3 = p[3];
        xrow[0]=a0.x; xrow[1]=a0.y; xrow[2]=a0.z; xrow[3]=a0.w;
        xrow[4]=a1.x; xrow[5]=a1.y; xrow[6]=a1.z; xrow[7]=a1.w;
        xrow[8]=a2.x; xrow[9]=a2.y; xrow[10]=a2.z; xrow[11]=a2.w;
        xrow[12]=a3.x; xrow[13]=a3.y; xrow[14]=a3.z; xrow[15]=a3.w;
        #pragma unroll
        for (int i = 0; i < 16; i++) sX[i][s] = xrow[i];
    }
    __syncthreads();

    u64 acc2[8];
    if (s < SEQ) {
        // YA = X @ B1, YF = X @ F2 (row s), packed f32x2
        {
            u64 ya2[8], yf2[8];
            #pragma unroll
            for (int h = 0; h < 8; h++) { ya2[h] = 0ull; yf2[h] = 0ull; }
            #pragma unroll
            for (int j = 0; j < 16; j++) {
                u64 xv = splat2(xrow[j]);
                const u64* b1r = (const u64*)sB1[j];
                const u64* f2r = (const u64*)sF2[j];
                #pragma unroll
                for (int h = 0; h < 8; h++) {
                    ya2[h] = ffma2(xv, b1r[h], ya2[h]);
                    yf2[h] = ffma2(xv, f2r[h], yf2[h]);
                }
            }
            u64* yaw = (u64*)sYA[s];
            u64* yfw = (u64*)sYF[s];
            #pragma unroll
            for (int h = 0; h < 8; h++) { yaw[h] = ya2[h]; yfw[h] = yf2[h]; }
        }

        // constant + fgcn_bl term
        float fblv = __ldg(fbl + s);
        #pragma unroll
        for (int h = 0; h < 8; h++)
            acc2[h] = pack2(sC0[2*h] + fblv * sCs[2*h], sC0[2*h+1] + fblv * sCs[2*h+1]);

        // spatial: gather mean over graph neighbors of c
        int r0 = g_rowptr[c], r1 = g_rowptr[c + 1];
        float mg[16];
        #pragma unroll
        for (int o = 0; o < 16; o++) mg[o] = 0.f;
        for (int e = r0; e < r1; e++) {
            int nb = g_col[e];
            const float4* p = (const float4*)(src + ((b * CAP + nb) * SEQ + s) * INV);
            float4 a0 = __ldg(p), a1 = __ldg(p + 1), a2 = __ldg(p + 2), a3 = __ldg(p + 3);
            mg[0]+=a0.x; mg[1]+=a0.y; mg[2]+=a0.z; mg[3]+=a0.w;
            mg[4]+=a1.x; mg[5]+=a1.y; mg[6]+=a1.z; mg[7]+=a1.w;
            mg[8]+=a2.x; mg[9]+=a2.y; mg[10]+=a2.z; mg[11]+=a2.w;
            mg[12]+=a3.x; mg[13]+=a3.y; mg[14]+=a3.z; mg[15]+=a3.w;
        }
        float sc = g_invdeg[c];
        #pragma unroll
        for (int j = 0; j < 16; j++) {
            u64 m  = splat2(mg[j] * sc);
            u64 xv = splat2(xrow[j]);
            const u64* g1r = (const u64*)sG1[j];
            const u64* g2r = (const u64*)sG2[j];
            #pragma unroll
            for (int h = 0; h < 8; h++) {
                acc2[h] = ffma2(m,  g1r[h], acc2[h]);
                acc2[h] = ffma2(xv, g2r[h], acc2[h]);
            }
        }

        // temporal: combined 5-tap conv with F3 folded in
        #pragma unroll
        for (int k = 0; k < 5; k++) {
            int sp = s + k - 2;
            if (sp >= 0 && sp < SEQ) {
                #pragma unroll
                for (int j = 0; j < 16; j++) {
                    u64 xv = splat2(sX[j][sp]);
                    const u64* vr = (const u64*)sV[k][j];
                    #pragma unroll
                    for (int h = 0; h < 8; h++) acc2[h] = ffma2(xv, vr[h], acc2[h]);
                }
            }
        }
    }
    __syncthreads();

    if (s < SEQ) {
        // big GEMM: acc += sum_t fWl[t][s]*YA[t][:] + fWr[t][s]*YF[t][:]  (f32x2)
        const float* wlp = fWl + s;
        const float* wrp = fWr + s;
        #pragma unroll 4
        for (int t = 0; t < SEQ; t++) {
            u64 av = splat2(__ldg(wlp + t * SEQ));
            u64 bv = splat2(__ldg(wrp + t * SEQ));
            const ulonglong2* yap = (const ulonglong2*)sYA[t];
            const ulonglong2* yfp = (const ulonglong2*)sYF[t];
            ulonglong2 u0 = yap[0], u1 = yap[1], u2 = yap[2], u3 = yap[3];
            ulonglong2 v0 = yfp[0], v1 = yfp[1], v2 = yfp[2], v3 = yfp[3];
            acc2[0] = ffma2(av, u0.x, acc2[0]); acc2[0] = ffma2(bv, v0.x, acc2[0]);
            acc2[1] = ffma2(av, u0.y, acc2[1]); acc2[1] = ffma2(bv, v0.y, acc2[1]);
            acc2[2] = ffma2(av, u1.x, acc2[2]); acc2[2] = ffma2(bv, v1.x, acc2[2]);
            acc2[3] = ffma2(av, u1.y, acc2[3]); acc2[3] = ffma2(bv, v1.y, acc2[3]);
            acc2[4] = ffma2(av, u2.x, acc2[4]); acc2[4] = ffma2(bv, v2.x, acc2[4]);
            acc2[5] = ffma2(av, u2.y, acc2[5]); acc2[5] = ffma2(bv, v2.y, acc2[5]);
            acc2[6] = ffma2(av, u3.x, acc2[6]); acc2[6] = ffma2(bv, v3.x, acc2[6]);
            acc2[7] = ffma2(av, u3.y, acc2[7]); acc2[7] = ffma2(bv, v3.y, acc2[7]);
        }

        // out = src + contributions (packed add, 128-bit stores)
        #pragma unroll
        for (int h = 0; h < 8; h++)
            acc2[h] = add2(acc2[h], pack2(xrow[2*h], xrow[2*h+1]));
        ulonglong2* po = (ulonglong2*)(out + base + s * INV);
        po[0] = make_ulonglong2(acc2[0], acc2[1]);
        po[1] = make_ulonglong2(acc2[2], acc2[3]);
        po[2] = make_ulonglong2(acc2[4], acc2[5]);
        po[3] = make_ulonglong2(acc2[6], acc2[7]);
    }
}

// ---------------- launch ----------------------------------------------------
extern "C" void kernel_launch(void* const* d_in, const int* in_sizes, int n_in,
                              void* d_out, int out_size) {
    const float* src = (const float*)d_in[0];
    const int*   gei = (const int*)d_in[1];
    const int*   fei = (const int*)d_in[2];
    const float* Wl  = (const float*)d_in[3];
    const float* bl  = (const float*)d_in[4];
    const float* Wr  = (const float*)d_in[5];
    const float* fWl = (const float*)d_in[6];
    const float* fbl = (const float*)d_in[7];
    const float* fWr = (const float*)d_in[8];
    const float* c1w = (const float*)d_in[9];
    const float* c2w = (const float*)d_in[10];
    const float* fcw = (const float*)d_in[11];
    const float* fcb = (const float*)d_in[12];

    prep_kernel<<<1, 256>>>(gei, fei, Wl, bl, Wr, c1w, c2w, fcw, fcb);
    dim3 grid(CAP, BZ);
    stconv_kernel<<<grid, NTHR>>>(src, fWl, fWr, fbl, (float*)d_out);
}

// round 4
// speedup vs baseline: 1.4275x; 1.4275x over previous
#include <cuda_runtime.h>

#define BZ   32
#define CAP  134
#define SEQ  144
#define INV  16
#define E_SP 1072
#define E_FT 64
#define NTHR 160
#define XSTR 160
#define YSTR 20   // padded row stride for sYA/sYF (bank-conflict-free STS)

// ---------------- device-global precomputed state (no cudaMalloc allowed) ----
__device__ int    g_rowptr[CAP + 1];
__device__ int    g_col[E_SP];
__device__ float  g_invdeg[CAP];
__device__ float  g_G1[INV][INV];   // Wl @ F1
__device__ float  g_G2[INV][INV];   // Wr @ F1
__device__ float  g_B1[INV][INV];   // A^T @ F2
__device__ float  g_F2[INV][INV];   // F2
__device__ float  g_V[5][INV][INV]; // combined conv taps folded with F3
__device__ float  g_csF2[INV];      // column sums of F2 (for fgcn_bl term)
__device__ float  g_const[INV];     // bl@F1 + fc_b
__device__ float2 g_W2[SEQ * SEQ];  // packed (fWl[t][s], fWr[t][s])

// ---------------- prep kernel: deterministic CSR + folded matrices ----------
__global__ void prep_kernel(const int* __restrict__ gei, const int* __restrict__ fei,
                            const float* __restrict__ Wl, const float* __restrict__ bl,
                            const float* __restrict__ Wr,
                            const float* __restrict__ c1w, const float* __restrict__ c2w,
                            const float* __restrict__ fcw, const float* __restrict__ fcb) {
    int tid = threadIdx.x; // 256 threads
    __shared__ int   s_deg[CAP];
    __shared__ int   s_cnt[INV][INV];
    __shared__ float s_A[INV][INV];

    if (tid < CAP) {
        int cnt = 0;
        for (int e = 0; e < E_SP; e++) if (gei[E_SP + e] == tid) cnt++;
        s_deg[tid] = cnt;
        g_invdeg[tid] = 1.0f / fmaxf((float)cnt, 1.0f);
    }
    __syncthreads();
    if (tid == 0) {
        int acc = 0;
        for (int c = 0; c < CAP; c++) { g_rowptr[c] = acc; acc += s_deg[c]; }
        g_rowptr[CAP] = acc;
    }
    __syncthreads();
    if (tid < CAP) {
        int k = g_rowptr[tid];
        for (int e = 0; e < E_SP; e++)
            if (gei[E_SP + e] == tid) g_col[k++] = gei[e];
    }
    {
        int i = tid >> 4, j = tid & 15;
        int cnt = 0;
        for (int e = 0; e < E_FT; e++)
            if (fei[E_FT + e] == i && fei[e] == j) cnt++;
        s_cnt[i][j] = cnt;
    }
    __syncthreads();
    {
        int i = tid >> 4, j = tid & 15;
        int dsum = 0;
        for (int jj = 0; jj < INV; jj++) dsum += s_cnt[i][jj];
        s_A[i][j] = (float)s_cnt[i][j] / fmaxf((float)dsum, 1.0f);
    }
    __syncthreads();
    {
        int r = tid >> 4, o = tid & 15;
        float g1 = 0.f, g2 = 0.f, b1 = 0.f;
        for (int i = 0; i < INV; i++) {
            float f1 = fcw[i * INV + o];
            float f2 = fcw[(INV + i) * INV + o];
            g1 += Wl[r * INV + i] * f1;
            g2 += Wr[r * INV + i] * f1;
            b1 += s_A[i][r] * f2;
        }
        g_G1[r][o] = g1; g_G2[r][o] = g2; g_B1[r][o] = b1;
        g_F2[r][o] = fcw[(INV + r) * INV + o];
        for (int k = 0; k < 5; k++) {
            float v = 0.f;
            for (int o2 = 0; o2 < INV; o2++) {
                float w5 = c2w[(o2 * INV + r) * 5 + k];
                if (k >= 1 && k <= 3) w5 += c1w[(o2 * INV + r) * 3 + (k - 1)];
                v += w5 * fcw[(32 + o2) * INV + o];
            }
            g_V[k][r][o] = v;
        }
        if (r == 0) {
            float cs = 0.f, cv = 0.f;
            for (int i = 0; i < INV; i++) {
                cs += fcw[(INV + i) * INV + o];
                cv += bl[i] * fcw[i * INV + o];
            }
            g_csF2[o] = cs;
            g_const[o] = cv + fcb[o];
        }
    }
}

// pack (fWl, fWr) into interleaved float2 so the hot loop does 1 LDG.64 not 2 LDG.32
__global__ void w2_kernel(const float* __restrict__ fWl, const float* __restrict__ fWr) {
    int i = blockIdx.x * blockDim.x + threadIdx.x;
    if (i < SEQ * SEQ) g_W2[i] = make_float2(fWl[i], fWr[i]);
}

// ---------------- main fused kernel: one (b,c) slice per block --------------
__global__ __launch_bounds__(NTHR, 4)
void stconv_kernel(const float* __restrict__ src,
                   const float* __restrict__ fbl,
                   float* __restrict__ out) {
    __shared__ __align__(16) float sX[INV][XSTR];      // transposed X: sX[i][s]
    __shared__ __align__(16) float sYA[SEQ][YSTR];     // X @ (A^T F2), padded rows
    __shared__ __align__(16) float sYF[SEQ][YSTR];     // X @ F2, padded rows
    __shared__ __align__(16) float sG1[INV][INV], sG2[INV][INV], sB1[INV][INV], sF2[INV][INV];
    __shared__ __align__(16) float sV[5][INV][INV];
    __shared__ float sCs[INV], sC0[INV];

    const int c = blockIdx.x, b = blockIdx.y;
    const int tid = threadIdx.x;
    const int s = tid;
    const int base = ((b * CAP + c) * SEQ) * INV;

    for (int idx = tid; idx < INV * INV; idx += NTHR) {
        int r = idx >> 4, o = idx & 15;
        sG1[r][o] = g_G1[r][o]; sG2[r][o] = g_G2[r][o];
        sB1[r][o] = g_B1[r][o]; sF2[r][o] = g_F2[r][o];
        #pragma unroll
        for (int k = 0; k < 5; k++) sV[k][r][o] = g_V[k][r][o];
        if (r == 0) { sCs[o] = g_csF2[o]; sC0[o] = g_const[o]; }
    }

    if (s < SEQ) {
        const float4* p = (const float4*)(src + base + s * INV);
        float4 a0 = p[0], a1 = p[1], a2 = p[2], a3 = p[3];
        sX[0][s]=a0.x;  sX[1][s]=a0.y;  sX[2][s]=a0.z;  sX[3][s]=a0.w;
        sX[4][s]=a1.x;  sX[5][s]=a1.y;  sX[6][s]=a1.z;  sX[7][s]=a1.w;
        sX[8][s]=a2.x;  sX[9][s]=a2.y;  sX[10][s]=a2.z; sX[11][s]=a2.w;
        sX[12][s]=a3.x; sX[13][s]=a3.y; sX[14][s]=a3.z; sX[15][s]=a3.w;
    }
    __syncthreads();

    float acc[16];
    if (s < SEQ) {
        // YA = X @ B1, YF = X @ F2 (row s) -> smem for the big-GEMM phase
        {
            float ya[16], yf[16];
            #pragma unroll
            for (int o = 0; o < 16; o++) { ya[o] = 0.f; yf[o] = 0.f; }
            #pragma unroll
            for (int j = 0; j < 16; j++) {
                float xv = sX[j][s];
                #pragma unroll
                for (int o = 0; o < 16; o++) {
                    ya[o] += xv * sB1[j][o];
                    yf[o] += xv * sF2[j][o];
                }
            }
            #pragma unroll
            for (int o = 0; o < 16; o++) { sYA[s][o] = ya[o]; sYF[s][o] = yf[o]; }
        }

        // constant + fgcn_bl term
        float fblv = __ldg(fbl + s);
        #pragma unroll
        for (int o = 0; o < 16; o++) acc[o] = sC0[o] + fblv * sCs[o];

        // spatial: gather mean over graph neighbors of c
        {
            int r0 = g_rowptr[c], r1 = g_rowptr[c + 1];
            float mg[16];
            #pragma unroll
            for (int o = 0; o < 16; o++) mg[o] = 0.f;
            for (int e = r0; e < r1; e++) {
                int nb = g_col[e];
                const float4* p = (const float4*)(src + ((b * CAP + nb) * SEQ + s) * INV);
                float4 a0 = __ldg(p), a1 = __ldg(p + 1), a2 = __ldg(p + 2), a3 = __ldg(p + 3);
                mg[0]+=a0.x; mg[1]+=a0.y; mg[2]+=a0.z; mg[3]+=a0.w;
                mg[4]+=a1.x; mg[5]+=a1.y; mg[6]+=a1.z; mg[7]+=a1.w;
                mg[8]+=a2.x; mg[9]+=a2.y; mg[10]+=a2.z; mg[11]+=a2.w;
                mg[12]+=a3.x; mg[13]+=a3.y; mg[14]+=a3.z; mg[15]+=a3.w;
            }
            float sc = g_invdeg[c];
            #pragma unroll
            for (int j = 0; j < 16; j++) {
                float m = mg[j] * sc;
                float xv = sX[j][s];
                #pragma unroll
                for (int o = 0; o < 16; o++) acc[o] += m * sG1[j][o] + xv * sG2[j][o];
            }
        }

        // temporal: combined 5-tap conv with F3 folded in
        #pragma unroll
        for (int k = 0; k < 5; k++) {
            int sp = s + k - 2;
            if (sp >= 0 && sp < SEQ) {
                #pragma unroll
                for (int j = 0; j < 16; j++) {
                    float xv = sX[j][sp];
                    #pragma unroll
                    for (int o = 0; o < 16; o++) acc[o] += xv * sV[k][j][o];
                }
            }
        }
    }
    __syncthreads();

    if (s < SEQ) {
        // big GEMM: acc += sum_t fWl[t][s]*YA[t][:] + fWr[t][s]*YF[t][:]
        const float2* wp = g_W2 + s;
        #pragma unroll 4
        for (int t = 0; t < SEQ; t++) {
            float2 w = __ldg(wp + t * SEQ);
            float a = w.x, bb = w.y;
            const float4* yap = (const float4*)sYA[t];
            const float4* yfp = (const float4*)sYF[t];
            float4 u0 = yap[0], u1 = yap[1], u2 = yap[2], u3 = yap[3];
            float4 v0 = yfp[0], v1 = yfp[1], v2 = yfp[2], v3 = yfp[3];
            acc[0]  += a*u0.x + bb*v0.x;  acc[1]  += a*u0.y + bb*v0.y;
            acc[2]  += a*u0.z + bb*v0.z;  acc[3]  += a*u0.w + bb*v0.w;
            acc[4]  += a*u1.x + bb*v1.x;  acc[5]  += a*u1.y + bb*v1.y;
            acc[6]  += a*u1.z + bb*v1.z;  acc[7]  += a*u1.w + bb*v1.w;
            acc[8]  += a*u2.x + bb*v2.x;  acc[9]  += a*u2.y + bb*v2.y;
            acc[10] += a*u2.z + bb*v2.z;  acc[11] += a*u2.w + bb*v2.w;
            acc[12] += a*u3.x + bb*v3.x;  acc[13] += a*u3.y + bb*v3.y;
            acc[14] += a*u3.z + bb*v3.z;  acc[15] += a*u3.w + bb*v3.w;
        }

        // out = src + contributions (x re-read from smem -> short register lifetime)
        float4* po = (float4*)(out + base + s * INV);
        po[0] = make_float4(sX[0][s]+acc[0],   sX[1][s]+acc[1],   sX[2][s]+acc[2],   sX[3][s]+acc[3]);
        po[1] = make_float4(sX[4][s]+acc[4],   sX[5][s]+acc[5],   sX[6][s]+acc[6],   sX[7][s]+acc[7]);
        po[2] = make_float4(sX[8][s]+acc[8],   sX[9][s]+acc[9],   sX[10][s]+acc[10], sX[11][s]+acc[11]);
        po[3] = make_float4(sX[12][s]+acc[12], sX[13][s]+acc[13], sX[14][s]+acc[14], sX[15][s]+acc[15]);
    }
}

// ---------------- launch ----------------------------------------------------
extern "C" void kernel_launch(void* const* d_in, const int* in_sizes, int n_in,
                              void* d_out, int out_size) {
    const float* src = (const float*)d_in[0];
    const int*   gei = (const int*)d_in[1];
    const int*   fei = (const int*)d_in[2];
    const float* Wl  = (const float*)d_in[3];
    const float* bl  = (const float*)d_in[4];
    const float* Wr  = (const float*)d_in[5];
    const float* fWl = (const float*)d_in[6];
    const float* fbl = (const float*)d_in[7];
    const float* fWr = (const float*)d_in[8];
    const float* c1w = (const float*)d_in[9];
    const float* c2w = (const float*)d_in[10];
    const float* fcw = (const float*)d_in[11];
    const float* fcb = (const float*)d_in[12];

    prep_kernel<<<1, 256>>>(gei, fei, Wl, bl, Wr, c1w, c2w, fcw, fcb);
    w2_kernel<<<(SEQ * SEQ + 255) / 256, 256>>>(fWl, fWr);
    dim3 grid(CAP, BZ);
    stconv_kernel<<<grid, NTHR>>>(src, fbl, (float*)d_out);
}